// round 5
// baseline (speedup 1.0000x reference)
#include <cuda_runtime.h>
#include <cuda_fp16.h>
#include <cstdint>

#define FDIM     512
#define MTILE    128
#define NTHREADS 512

// Q in MMA-fragment-ready layout: g_Qf[K][N8][lane] = {b0, b1} for
// mma.m16n8k16.row.col. K = k16 step (0..31), N8 = n8 tile (0..63).
// b0 lane l = { Q[K*16 + 2*(l&3)][N8*8 + (l>>2)], Q[K*16 + 2*(l&3)+1][...] }
// b1 = same with k += 8.  (Identical to what ldmatrix.x4.trans delivered.)
__device__ uint2 g_Qf[32 * 64 * 32];

// ---------------- smem: A tile only + partials ----------------
#define SMEM_PART 131072
#define SMEM_TOTAL (131072 + 512)

__device__ __forceinline__ uint32_t smem_u32(const void* p) {
    uint32_t a;
    asm("{ .reg .u64 t; cvta.to.shared.u64 t, %1; cvt.u32.u64 %0, t; }" : "=r"(a) : "l"(p));
    return a;
}
__device__ __forceinline__ void ldsm_x4(uint32_t* r, uint32_t addr) {
    asm volatile("ldmatrix.sync.aligned.m8n8.x4.shared.b16 {%0,%1,%2,%3}, [%4];"
                 : "=r"(r[0]), "=r"(r[1]), "=r"(r[2]), "=r"(r[3]) : "r"(addr));
}
__device__ __forceinline__ void mma_16816(float* d, const uint32_t* a, uint32_t b0, uint32_t b1) {
    asm volatile(
        "mma.sync.aligned.m16n8k16.row.col.f32.f16.f16.f32 "
        "{%0,%1,%2,%3}, {%4,%5,%6,%7}, {%8,%9}, {%0,%1,%2,%3};"
        : "+f"(d[0]), "+f"(d[1]), "+f"(d[2]), "+f"(d[3])
        : "r"(a[0]), "r"(a[1]), "r"(a[2]), "r"(a[3]), "r"(b0), "r"(b1));
}
__device__ __forceinline__ uint32_t pack_h2(float lo, float hi) {
    uint32_t p;
    asm("cvt.rn.f16x2.f32 %0, %1, %2;" : "=r"(p) : "f"(hi), "f"(lo));
    return p;
}

// ---------------- Q fp32 -> fragment-layout fp16 ----------------
__global__ void convert_q_frag(const float* __restrict__ Q) {
    int idx  = blockIdx.x * blockDim.x + threadIdx.x;   // 65536 threads
    int lane = idx & 31;
    int N8   = (idx >> 5) & 63;
    int K    = idx >> 11;
    int n  = N8 * 8 + (lane >> 2);
    int k0 = K * 16 + 2 * (lane & 3);
    uint2 f;
    f.x = pack_h2(Q[k0 * FDIM + n],       Q[(k0 + 1) * FDIM + n]);
    f.y = pack_h2(Q[(k0 + 8) * FDIM + n], Q[(k0 + 9) * FDIM + n]);
    g_Qf[idx] = f;
}

// ---------------- fused triangular GEMM + per-row bilinear dot ----------------
// 16 warps: khalf = wid>>3 (2-way K split), warp_m = (wid>>2)&1 (m64 slab),
// warp_n = wid&3 (n32 quarter of the 128-wide n-block). Warp tile m64 x n32.
__global__ __launch_bounds__(NTHREADS, 1)
void bilinear_kernel(const float* __restrict__ x, float* __restrict__ out) {
    extern __shared__ char smem[];
    const uint32_t a_base = smem_u32(smem);
    float* partial = (float*)(smem + SMEM_PART);

    const int tid  = threadIdx.x;
    const int lane = tid & 31;
    const int wid  = tid >> 5;
    const int khalf  = wid >> 3;
    const int warp_m = (wid >> 2) & 1;
    const int warp_n = wid & 3;
    const size_t row0 = (size_t)blockIdx.x * MTILE;

    if (tid < MTILE) partial[tid] = 0.f;

    // ---- Load A tile: x[row0..+127, 0..511] fp32 -> fp16, swizzled, 1024B pitch ----
    #pragma unroll 4
    for (int i = 0; i < 16; ++i) {
        int item = tid + i * NTHREADS;
        int row = item >> 6, c = item & 63;
        const float4* src = (const float4*)(x + (row0 + row) * FDIM + c * 8);
        float4 f0 = src[0];
        float4 f1 = src[1];
        uint4 h;
        h.x = pack_h2(f0.x, f0.y);
        h.y = pack_h2(f0.z, f0.w);
        h.z = pack_h2(f1.x, f1.y);
        h.w = pack_h2(f1.z, f1.w);
        *(uint4*)(smem + row * 1024 + ((c ^ (row & 7)) << 4)) = h;
    }
    __syncthreads();   // the ONLY barrier before the epilogue write-out

    float acc[4][4][4];
    #pragma unroll
    for (int mt = 0; mt < 4; ++mt)
        #pragma unroll
        for (int nt = 0; nt < 4; ++nt)
            #pragma unroll
            for (int v = 0; v < 4; ++v) acc[mt][nt][v] = 0.f;

    for (int j = 0; j < 4; ++j) {
        const int span = 4 * (j + 1);          // K-steps per half for this n-block
        const int Kbeg = khalf * span;
        const int Kend = Kbeg + span;
        const int N8b  = j * 16 + warp_n * 4;  // first n8 tile of this warp

        // double-buffered B fragments straight from gmem (L1/L2-hot)
        uint2 b[2][4];
        #pragma unroll
        for (int nt = 0; nt < 4; ++nt)
            b[0][nt] = __ldg(&g_Qf[(Kbeg * 64 + N8b + nt) * 32 + lane]);

        for (int K = Kbeg; K < Kend; ++K) {
            const int cur = (K - Kbeg) & 1;
            if (K + 1 < Kend) {
                #pragma unroll
                for (int nt = 0; nt < 4; ++nt)
                    b[cur ^ 1][nt] = __ldg(&g_Qf[((K + 1) * 64 + N8b + nt) * 32 + lane]);
            }
            uint32_t afr[4][4];
            #pragma unroll
            for (int mt = 0; mt < 4; ++mt) {
                int rowm = warp_m * 64 + mt * 16 + (lane & 15);
                int ck = K * 2 + (lane >> 4);
                ldsm_x4(afr[mt], a_base + rowm * 1024 + ((ck ^ (rowm & 7)) << 4));
            }
            #pragma unroll
            for (int mt = 0; mt < 4; ++mt)
                #pragma unroll
                for (int nt = 0; nt < 4; ++nt)
                    mma_16816(acc[mt][nt], afr[mt], b[cur][nt].x, b[cur][nt].y);
        }

        // ---- fused epilogue for n-block j: out[m] += sum_n t[m,n] * x[m,n] ----
        #pragma unroll
        for (int mt = 0; mt < 4; ++mt) {
            #pragma unroll
            for (int h = 0; h < 2; ++h) {
                int m_loc = warp_m * 64 + mt * 16 + h * 8 + (lane >> 2);
                const float* xrow = x + (row0 + m_loc) * FDIM + j * 128
                                    + warp_n * 32 + (lane & 3) * 2;
                float s = 0.f;
                #pragma unroll
                for (int nt = 0; nt < 4; ++nt) {
                    float2 xv = *(const float2*)(xrow + nt * 8);
                    s += acc[mt][nt][h * 2 + 0] * xv.x + acc[mt][nt][h * 2 + 1] * xv.y;
                }
                s += __shfl_xor_sync(0xFFFFFFFFu, s, 1);
                s += __shfl_xor_sync(0xFFFFFFFFu, s, 2);
                if ((lane & 3) == 0) atomicAdd(&partial[m_loc], s);
            }
        }
        #pragma unroll
        for (int mt = 0; mt < 4; ++mt)
            #pragma unroll
            for (int nt = 0; nt < 4; ++nt)
                #pragma unroll
                for (int v = 0; v < 4; ++v) acc[mt][nt][v] = 0.f;
    }

    __syncthreads();
    if (tid < MTILE) out[row0 + tid] = partial[tid];
}

// ---------------- launch ----------------
extern "C" void kernel_launch(void* const* d_in, const int* in_sizes, int n_in,
                              void* d_out, int out_size) {
    const float* x = (const float*)d_in[0];
    const float* Q = (const float*)d_in[1];
    if (n_in >= 2 && in_sizes[0] == FDIM * FDIM && in_sizes[1] != FDIM * FDIM) {
        const float* t = x; x = Q; Q = t;
    }
    float* out = (float*)d_out;

    cudaFuncSetAttribute(bilinear_kernel,
                         cudaFuncAttributeMaxDynamicSharedMemorySize, SMEM_TOTAL);

    convert_q_frag<<<256, 256>>>(Q);
    bilinear_kernel<<<131072 / MTILE, NTHREADS, SMEM_TOTAL>>>(x, out);
}

// round 7
// speedup vs baseline: 1.3127x; 1.3127x over previous
#include <cuda_runtime.h>
#include <cuda_fp16.h>
#include <cstdint>

#define FDIM     512
#define MTILE    64
#define NTHREADS 256
#define NCHUNKS  20          // triangular: sum over j of 2*(j+1)

// Q converted to fp16, same [k][n] layout (row-major k, n contiguous).
__device__ __half g_Qh[FDIM * FDIM];

// ---------------- smem layout (per CTA ~112.5KB -> 2 CTAs/SM) ----------------
// A tile: 64 rows x 512 halves (1024B pitch, swizzled) = 64KB
// B ring: 3 x (64 rows x 128 halves, 256B pitch, swizzled) = 48KB
#define SMEM_A    0
#define SMEM_B    65536
#define SMEM_PART (65536 + 49152)
#define SMEM_TOTAL (SMEM_PART + 256)

__device__ __forceinline__ uint32_t smem_u32(const void* p) {
    uint32_t a;
    asm("{ .reg .u64 t; cvta.to.shared.u64 t, %1; cvt.u32.u64 %0, t; }" : "=r"(a) : "l"(p));
    return a;
}
__device__ __forceinline__ void ldsm_x4(uint32_t* r, uint32_t addr) {
    asm volatile("ldmatrix.sync.aligned.m8n8.x4.shared.b16 {%0,%1,%2,%3}, [%4];"
                 : "=r"(r[0]), "=r"(r[1]), "=r"(r[2]), "=r"(r[3]) : "r"(addr));
}
__device__ __forceinline__ void ldsm_x4_trans(uint32_t* r, uint32_t addr) {
    asm volatile("ldmatrix.sync.aligned.m8n8.x4.trans.shared.b16 {%0,%1,%2,%3}, [%4];"
                 : "=r"(r[0]), "=r"(r[1]), "=r"(r[2]), "=r"(r[3]) : "r"(addr));
}
__device__ __forceinline__ void mma_16816(float* d, const uint32_t* a, uint32_t b0, uint32_t b1) {
    asm volatile(
        "mma.sync.aligned.m16n8k16.row.col.f32.f16.f16.f32 "
        "{%0,%1,%2,%3}, {%4,%5,%6,%7}, {%8,%9}, {%0,%1,%2,%3};"
        : "+f"(d[0]), "+f"(d[1]), "+f"(d[2]), "+f"(d[3])
        : "r"(a[0]), "r"(a[1]), "r"(a[2]), "r"(a[3]), "r"(b0), "r"(b1));
}
__device__ __forceinline__ void cp_async16(uint32_t saddr, const void* gaddr) {
    asm volatile("cp.async.cg.shared.global [%0], [%1], 16;" :: "r"(saddr), "l"(gaddr));
}
__device__ __forceinline__ uint32_t pack_h2(float lo, float hi) {
    uint32_t p;
    asm("cvt.rn.f16x2.f32 %0, %1, %2;" : "=r"(p) : "f"(hi), "f"(lo));
    return p;
}

// chunk index -> (n-block j, k-chunk kc) for the triangular schedule
__device__ __forceinline__ int chunk_j(int c) {
    return (c < 2) ? 0 : (c < 6) ? 1 : (c < 12) ? 2 : 3;
}
__device__ __forceinline__ int chunk_kc(int c) {
    int j = chunk_j(c);
    int base = (j == 0) ? 0 : (j == 1) ? 2 : (j == 2) ? 6 : 12;
    return c - base;
}

// ---------------- Q fp32 -> fp16 convert ----------------
__global__ void convert_q_kernel(const float* __restrict__ Q) {
    int i = blockIdx.x * blockDim.x + threadIdx.x;
    float4 v = ((const float4*)Q)[i];
    ((uint32_t*)g_Qh)[i * 2 + 0] = pack_h2(v.x, v.y);
    ((uint32_t*)g_Qh)[i * 2 + 1] = pack_h2(v.z, v.w);
}

// ---------------- fused triangular GEMM + per-row bilinear dot ----------------
// 8 warps: warp_m = wid&1 (m32 slab of the 64-row tile),
//          warp_n = wid>>1 (n32 quarter of the 128-wide n-block).
__global__ __launch_bounds__(NTHREADS, 2)
void bilinear_kernel(const float* __restrict__ x, float* __restrict__ out) {
    extern __shared__ char smem[];
    const uint32_t sbase  = smem_u32(smem);
    const uint32_t a_base = sbase + SMEM_A;
    const uint32_t b_base = sbase + SMEM_B;
    float* partial = (float*)(smem + SMEM_PART);

    const int tid  = threadIdx.x;
    const int lane = tid & 31;
    const int wid  = tid >> 5;
    const int warp_m = wid & 1;
    const int warp_n = wid >> 1;
    const size_t row0 = (size_t)blockIdx.x * MTILE;

    if (tid < MTILE) partial[tid] = 0.f;

    // ---- B chunk producer: Q[kc*64 .. +63][j*128 .. +127] fp16 via cp.async ----
    auto issue_b = [&](int c, int buf) {
        int j = chunk_j(c), kc = chunk_kc(c);
        uint32_t dst = b_base + buf * 16384;
        const __half* gb = g_Qh + (size_t)(kc * 64) * FDIM + j * 128;
        #pragma unroll
        for (int i = 0; i < 4; ++i) {
            int item = tid + i * NTHREADS;
            int r = item >> 4, cn = item & 15;
            cp_async16(dst + r * 256 + ((cn ^ (r & 7)) << 4), gb + r * FDIM + cn * 8);
        }
        asm volatile("cp.async.commit_group;" ::: "memory");
    };

    issue_b(0, 0);
    issue_b(1, 1);

    // ---- Load A tile: x[row0..+63, 0..511] fp32 -> fp16, swizzled ----
    // 64 rows x 64 chunks(16B) = 4096 items, 16 per thread.
    #pragma unroll 4
    for (int i = 0; i < 16; ++i) {
        int item = tid + i * NTHREADS;
        int row = item >> 6, c = item & 63;
        const float4* src = (const float4*)(x + (row0 + row) * FDIM + c * 8);
        float4 f0 = src[0];
        float4 f1 = src[1];
        uint4 h;
        h.x = pack_h2(f0.x, f0.y);
        h.y = pack_h2(f0.z, f0.w);
        h.z = pack_h2(f1.x, f1.y);
        h.w = pack_h2(f1.z, f1.w);
        *(uint4*)(smem + row * 1024 + ((c ^ (row & 7)) << 4)) = h;
    }

    float acc[2][4][4];
    #pragma unroll
    for (int mt = 0; mt < 2; ++mt)
        #pragma unroll
        for (int nt = 0; nt < 4; ++nt)
            #pragma unroll
            for (int v = 0; v < 4; ++v) acc[mt][nt][v] = 0.f;

    for (int c = 0; c < NCHUNKS; ++c) {
        if (c < NCHUNKS - 1) asm volatile("cp.async.wait_group 1;" ::: "memory");
        else                 asm volatile("cp.async.wait_group 0;" ::: "memory");
        __syncthreads();   // chunk c visible; buf (c+2)%3 fully consumed

        if (c + 2 < NCHUNKS) issue_b(c + 2, (c + 2) % 3);

        const uint32_t bbuf = b_base + (c % 3) * 16384;
        const int kc = chunk_kc(c);

        #pragma unroll
        for (int ks = 0; ks < 4; ++ks) {
            uint32_t afr[2][4];
            #pragma unroll
            for (int mt = 0; mt < 2; ++mt) {
                int rowm = warp_m * 32 + mt * 16 + (lane & 15);
                int ck = kc * 8 + ks * 2 + (lane >> 4);
                ldsm_x4(afr[mt], a_base + rowm * 1024 + ((ck ^ (rowm & 7)) << 4));
            }
            uint32_t bfr[2][4];
            #pragma unroll
            for (int np = 0; np < 2; ++np) {
                int krow = ks * 16 + (lane & 15);
                int cn = warp_n * 4 + np * 2 + (lane >> 4);
                ldsm_x4_trans(bfr[np], bbuf + krow * 256 + ((cn ^ (krow & 7)) << 4));
            }
            #pragma unroll
            for (int mt = 0; mt < 2; ++mt)
                #pragma unroll
                for (int nt = 0; nt < 4; ++nt)
                    mma_16816(acc[mt][nt], afr[mt],
                              bfr[nt >> 1][(nt & 1) * 2], bfr[nt >> 1][(nt & 1) * 2 + 1]);
        }

        // ---- End of n-block j: fused epilogue, out[m] += sum_n t[m,n]*x[m,n] ----
        if (c == 1 || c == 5 || c == 11 || c == NCHUNKS - 1) {
            const int j = chunk_j(c);
            #pragma unroll
            for (int mt = 0; mt < 2; ++mt) {
                #pragma unroll
                for (int h = 0; h < 2; ++h) {
                    int m_loc = warp_m * 32 + mt * 16 + h * 8 + (lane >> 2);
                    const float* xrow = x + (row0 + m_loc) * FDIM + j * 128
                                        + warp_n * 32 + (lane & 3) * 2;
                    float s = 0.f;
                    #pragma unroll
                    for (int nt = 0; nt < 4; ++nt) {
                        float2 xv = *(const float2*)(xrow + nt * 8);
                        s += acc[mt][nt][h * 2 + 0] * xv.x + acc[mt][nt][h * 2 + 1] * xv.y;
                    }
                    s += __shfl_xor_sync(0xFFFFFFFFu, s, 1);
                    s += __shfl_xor_sync(0xFFFFFFFFu, s, 2);
                    if ((lane & 3) == 0) atomicAdd(&partial[m_loc], s);
                }
            }
            #pragma unroll
            for (int mt = 0; mt < 2; ++mt)
                #pragma unroll
                for (int nt = 0; nt < 4; ++nt)
                    #pragma unroll
                    for (int v = 0; v < 4; ++v) acc[mt][nt][v] = 0.f;
        }
    }

    __syncthreads();
    if (tid < MTILE) out[row0 + tid] = partial[tid];
}

// ---------------- launch ----------------
extern "C" void kernel_launch(void* const* d_in, const int* in_sizes, int n_in,
                              void* d_out, int out_size) {
    const float* x = (const float*)d_in[0];
    const float* Q = (const float*)d_in[1];
    if (n_in >= 2 && in_sizes[0] == FDIM * FDIM && in_sizes[1] != FDIM * FDIM) {
        const float* t = x; x = Q; Q = t;
    }
    float* out = (float*)d_out;

    cudaFuncSetAttribute(bilinear_kernel,
                         cudaFuncAttributeMaxDynamicSharedMemorySize, SMEM_TOTAL);

    convert_q_kernel<<<(FDIM * FDIM / 4) / 256, 256>>>(Q);
    bilinear_kernel<<<131072 / MTILE, NTHREADS, SMEM_TOTAL>>>(x, out);
}

// round 8
// speedup vs baseline: 1.4326x; 1.0913x over previous
#include <cuda_runtime.h>
#include <cuda_fp16.h>
#include <cstdint>

#define FDIM     512
#define MTILE    64
#define NTHREADS 256
#define NCHUNKS  20          // triangular: sum over j of 2*(j+1)

// Q converted to fp16, same [k][n] layout (row-major k, n contiguous).
__device__ __half g_Qh[FDIM * FDIM];

// ---------------- smem layout (per CTA ~112.5KB -> 2 CTAs/SM) ----------------
#define SMEM_A    0
#define SMEM_B    65536
#define SMEM_PART (65536 + 49152)
#define SMEM_TOTAL (SMEM_PART + 256)

__device__ __forceinline__ uint32_t smem_u32(const void* p) {
    uint32_t a;
    asm("{ .reg .u64 t; cvta.to.shared.u64 t, %1; cvt.u32.u64 %0, t; }" : "=r"(a) : "l"(p));
    return a;
}
__device__ __forceinline__ void ldsm_x4(uint32_t* r, uint32_t addr) {
    asm volatile("ldmatrix.sync.aligned.m8n8.x4.shared.b16 {%0,%1,%2,%3}, [%4];"
                 : "=r"(r[0]), "=r"(r[1]), "=r"(r[2]), "=r"(r[3]) : "r"(addr));
}
__device__ __forceinline__ void ldsm_x4_trans(uint32_t* r, uint32_t addr) {
    asm volatile("ldmatrix.sync.aligned.m8n8.x4.trans.shared.b16 {%0,%1,%2,%3}, [%4];"
                 : "=r"(r[0]), "=r"(r[1]), "=r"(r[2]), "=r"(r[3]) : "r"(addr));
}
__device__ __forceinline__ void mma_16816(float* d, const uint32_t* a, uint32_t b0, uint32_t b1) {
    asm volatile(
        "mma.sync.aligned.m16n8k16.row.col.f32.f16.f16.f32 "
        "{%0,%1,%2,%3}, {%4,%5,%6,%7}, {%8,%9}, {%0,%1,%2,%3};"
        : "+f"(d[0]), "+f"(d[1]), "+f"(d[2]), "+f"(d[3])
        : "r"(a[0]), "r"(a[1]), "r"(a[2]), "r"(a[3]), "r"(b0), "r"(b1));
}
__device__ __forceinline__ void cp_async16(uint32_t saddr, const void* gaddr) {
    asm volatile("cp.async.cg.shared.global [%0], [%1], 16;" :: "r"(saddr), "l"(gaddr));
}
__device__ __forceinline__ uint32_t pack_h2(float lo, float hi) {
    uint32_t p;
    asm("cvt.rn.f16x2.f32 %0, %1, %2;" : "=r"(p) : "f"(hi), "f"(lo));
    return p;
}

__device__ __forceinline__ int chunk_j(int c) {
    return (c < 2) ? 0 : (c < 6) ? 1 : (c < 12) ? 2 : 3;
}
__device__ __forceinline__ int chunk_kc(int c) {
    int j = chunk_j(c);
    int base = (j == 0) ? 0 : (j == 1) ? 2 : (j == 2) ? 6 : 12;
    return c - base;
}

// ---------------- Q fp32 -> fp16 convert ----------------
__global__ void convert_q_kernel(const float* __restrict__ Q) {
    int i = blockIdx.x * blockDim.x + threadIdx.x;
    float4 v = ((const float4*)Q)[i];
    ((uint32_t*)g_Qh)[i * 2 + 0] = pack_h2(v.x, v.y);
    ((uint32_t*)g_Qh)[i * 2 + 1] = pack_h2(v.z, v.w);
}

// ---------------- fused triangular GEMM + per-row bilinear dot ----------------
__global__ __launch_bounds__(NTHREADS, 2)
void bilinear_kernel(const float* __restrict__ x, float* __restrict__ out) {
    extern __shared__ char smem[];
    const uint32_t sbase  = smem_u32(smem);
    const uint32_t a_base = sbase + SMEM_A;
    const uint32_t b_base = sbase + SMEM_B;
    float* partial = (float*)(smem + SMEM_PART);

    const int tid  = threadIdx.x;
    const int lane = tid & 31;
    const int wid  = tid >> 5;
    const int warp_m = wid & 1;
    const int warp_n = wid >> 1;
    const size_t row0 = (size_t)blockIdx.x * MTILE;

    if (tid < MTILE) partial[tid] = 0.f;

    auto issue_b = [&](int c, int buf) {
        int j = chunk_j(c), kc = chunk_kc(c);
        uint32_t dst = b_base + buf * 16384;
        const __half* gb = g_Qh + (size_t)(kc * 64) * FDIM + j * 128;
        #pragma unroll
        for (int i = 0; i < 4; ++i) {
            int item = tid + i * NTHREADS;
            int r = item >> 4, cn = item & 15;
            cp_async16(dst + r * 256 + ((cn ^ (r & 7)) << 4), gb + r * FDIM + cn * 8);
        }
        asm volatile("cp.async.commit_group;" ::: "memory");
    };

    issue_b(0, 0);
    issue_b(1, 1);

    // ---- Load A tile: x[row0..+63, 0..511] fp32 -> fp16, swizzled ----
    #pragma unroll 4
    for (int i = 0; i < 16; ++i) {
        int item = tid + i * NTHREADS;
        int row = item >> 6, c = item & 63;
        const float4* src = (const float4*)(x + (row0 + row) * FDIM + c * 8);
        float4 f0 = src[0];
        float4 f1 = src[1];
        uint4 h;
        h.x = pack_h2(f0.x, f0.y);
        h.y = pack_h2(f0.z, f0.w);
        h.z = pack_h2(f1.x, f1.y);
        h.w = pack_h2(f1.z, f1.w);
        *(uint4*)(smem + row * 1024 + ((c ^ (row & 7)) << 4)) = h;
    }

    float acc[2][4][4];
    #pragma unroll
    for (int mt = 0; mt < 2; ++mt)
        #pragma unroll
        for (int nt = 0; nt < 4; ++nt)
            #pragma unroll
            for (int v = 0; v < 4; ++v) acc[mt][nt][v] = 0.f;

    // Fragment loader for one ks within a chunk (into a given reg buffer)
    auto load_frags = [&](uint32_t bbuf, int kc, int ks,
                          uint32_t afr[2][4], uint32_t bfr[2][4]) {
        #pragma unroll
        for (int mt = 0; mt < 2; ++mt) {
            int rowm = warp_m * 32 + mt * 16 + (lane & 15);
            int ck = kc * 8 + ks * 2 + (lane >> 4);
            ldsm_x4(afr[mt], a_base + rowm * 1024 + ((ck ^ (rowm & 7)) << 4));
        }
        #pragma unroll
        for (int np = 0; np < 2; ++np) {
            int krow = ks * 16 + (lane & 15);
            int cn = warp_n * 4 + np * 2 + (lane >> 4);
            ldsm_x4_trans(bfr[np], bbuf + krow * 256 + ((cn ^ (krow & 7)) << 4));
        }
    };

    uint32_t afr[2][2][4], bfr[2][2][4];   // [buf][...]

    for (int c = 0; c < NCHUNKS; ++c) {
        if (c < NCHUNKS - 1) asm volatile("cp.async.wait_group 1;" ::: "memory");
        else                 asm volatile("cp.async.wait_group 0;" ::: "memory");
        __syncthreads();

        if (c + 2 < NCHUNKS) issue_b(c + 2, (c + 2) % 3);

        const uint32_t bbuf = b_base + (c % 3) * 16384;
        const int kc = chunk_kc(c);

        // software-pipelined ks loop: load ks+1 while issuing ks's MMAs
        load_frags(bbuf, kc, 0, afr[0], bfr[0]);
        #pragma unroll
        for (int ks = 0; ks < 4; ++ks) {
            const int cur = ks & 1;
            if (ks < 3) load_frags(bbuf, kc, ks + 1, afr[cur ^ 1], bfr[cur ^ 1]);
            #pragma unroll
            for (int mt = 0; mt < 2; ++mt)
                #pragma unroll
                for (int nt = 0; nt < 4; ++nt)
                    mma_16816(acc[mt][nt], afr[cur][mt],
                              bfr[cur][nt >> 1][(nt & 1) * 2],
                              bfr[cur][nt >> 1][(nt & 1) * 2 + 1]);
        }

        // ---- End of n-block j: fused epilogue using fp16 x from smem A-tile ----
        if (c == 1 || c == 5 || c == 11 || c == NCHUNKS - 1) {
            const int j = chunk_j(c);
            #pragma unroll
            for (int mt = 0; mt < 2; ++mt) {
                #pragma unroll
                for (int h = 0; h < 2; ++h) {
                    int m_loc = warp_m * 32 + mt * 16 + h * 8 + (lane >> 2);
                    uint32_t rowb = a_base + m_loc * 1024;
                    float s = 0.f;
                    #pragma unroll
                    for (int nt = 0; nt < 4; ++nt) {
                        int cch = j * 16 + warp_n * 4 + nt;   // 16B chunk holding n..n+7
                        uint32_t addr = rowb + ((cch ^ (m_loc & 7)) << 4) + (lane & 3) * 4;
                        uint32_t h2raw;
                        asm volatile("ld.shared.b32 %0, [%1];" : "=r"(h2raw) : "r"(addr));
                        float2 xv = __half22float2(*(__half2*)&h2raw);
                        s += acc[mt][nt][h * 2 + 0] * xv.x + acc[mt][nt][h * 2 + 1] * xv.y;
                    }
                    s += __shfl_xor_sync(0xFFFFFFFFu, s, 1);
                    s += __shfl_xor_sync(0xFFFFFFFFu, s, 2);
                    if ((lane & 3) == 0) atomicAdd(&partial[m_loc], s);
                }
            }
            #pragma unroll
            for (int mt = 0; mt < 2; ++mt)
                #pragma unroll
                for (int nt = 0; nt < 4; ++nt)
                    #pragma unroll
                    for (int v = 0; v < 4; ++v) acc[mt][nt][v] = 0.f;
        }
    }

    __syncthreads();
    if (tid < MTILE) out[row0 + tid] = partial[tid];
}

// ---------------- launch ----------------
extern "C" void kernel_launch(void* const* d_in, const int* in_sizes, int n_in,
                              void* d_out, int out_size) {
    const float* x = (const float*)d_in[0];
    const float* Q = (const float*)d_in[1];
    if (n_in >= 2 && in_sizes[0] == FDIM * FDIM && in_sizes[1] != FDIM * FDIM) {
        const float* t = x; x = Q; Q = t;
    }
    float* out = (float*)d_out;

    cudaFuncSetAttribute(bilinear_kernel,
                         cudaFuncAttributeMaxDynamicSharedMemorySize, SMEM_TOTAL);

    convert_q_kernel<<<(FDIM * FDIM / 4) / 256, 256>>>(Q);
    bilinear_kernel<<<131072 / MTILE, NTHREADS, SMEM_TOTAL>>>(x, out);
}

// round 11
// speedup vs baseline: 1.8134x; 1.2659x over previous
#include <cuda_runtime.h>
#include <cuda_fp16.h>
#include <cstdint>

#define FDIM     512
#define MTILE    64
#define NTHREADS 256

// Q in MMA-fragment-ready layout: g_Qf[K][N8][lane] = {b0, b1} for
// mma.m16n8k16.row.col. K = k16 step (0..31), N8 = n8 tile (0..63).
// b0 lane l = { Q[K*16 + 2*(l&3)][N8*8 + (l>>2)], Q[K*16 + 2*(l&3)+1][same n] }
// b1 = same with k += 8.  (Layout proven correct in an earlier passing round.)
__device__ uint2 g_Qf[32 * 64 * 32];

// ---------------- smem: A tile (64KB) + partials -> 2 CTAs/SM ----------------
#define SMEM_PART 65536
#define SMEM_TOTAL (65536 + 256)

__device__ __forceinline__ uint32_t smem_u32(const void* p) {
    uint32_t a;
    asm("{ .reg .u64 t; cvta.to.shared.u64 t, %1; cvt.u32.u64 %0, t; }" : "=r"(a) : "l"(p));
    return a;
}
__device__ __forceinline__ void ldsm_x4(uint32_t* r, uint32_t addr) {
    asm volatile("ldmatrix.sync.aligned.m8n8.x4.shared.b16 {%0,%1,%2,%3}, [%4];"
                 : "=r"(r[0]), "=r"(r[1]), "=r"(r[2]), "=r"(r[3]) : "r"(addr));
}
__device__ __forceinline__ void mma_16816(float* d, const uint32_t* a, uint32_t b0, uint32_t b1) {
    asm volatile(
        "mma.sync.aligned.m16n8k16.row.col.f32.f16.f16.f32 "
        "{%0,%1,%2,%3}, {%4,%5,%6,%7}, {%8,%9}, {%0,%1,%2,%3};"
        : "+f"(d[0]), "+f"(d[1]), "+f"(d[2]), "+f"(d[3])
        : "r"(a[0]), "r"(a[1]), "r"(a[2]), "r"(a[3]), "r"(b0), "r"(b1));
}
__device__ __forceinline__ uint32_t pack_h2(float lo, float hi) {
    uint32_t p;
    asm("cvt.rn.f16x2.f32 %0, %1, %2;" : "=r"(p) : "f"(hi), "f"(lo));
    return p;
}

// ---------------- Q fp32 -> fragment-layout fp16 ----------------
__global__ void convert_q_frag(const float* __restrict__ Q) {
    int idx  = blockIdx.x * blockDim.x + threadIdx.x;   // 65536 threads
    int lane = idx & 31;
    int N8   = (idx >> 5) & 63;
    int K    = idx >> 11;
    int n  = N8 * 8 + (lane >> 2);
    int k0 = K * 16 + 2 * (lane & 3);
    uint2 f;
    f.x = pack_h2(Q[k0 * FDIM + n],       Q[(k0 + 1) * FDIM + n]);
    f.y = pack_h2(Q[(k0 + 8) * FDIM + n], Q[(k0 + 9) * FDIM + n]);
    g_Qf[idx] = f;
}

// ---------------- fused triangular GEMM + per-row bilinear dot ----------------
// 8 warps: warp_m = wid&1 (m32 slab), warp_n = wid>>1 (n32 quarter of the
// 128-wide n-block). B fragments stream from L2 (g_Qf) through a 4-deep
// register ring; NO barriers and NO smem traffic for B in the mainloop.
__global__ __launch_bounds__(NTHREADS, 2)
void bilinear_kernel(const float* __restrict__ x, float* __restrict__ out) {
    extern __shared__ char smem[];
    const uint32_t a_base = smem_u32(smem);
    float* partial = (float*)(smem + SMEM_PART);

    const int tid  = threadIdx.x;
    const int lane = tid & 31;
    const int wid  = tid >> 5;
    const int warp_m = wid & 1;
    const int warp_n = wid >> 1;
    const size_t row0 = (size_t)blockIdx.x * MTILE;

    if (tid < MTILE) partial[tid] = 0.f;

    // ---- Load A tile: x[row0..+63, 0..511] fp32 -> fp16, swizzled, 1024B pitch ----
    #pragma unroll 4
    for (int i = 0; i < 16; ++i) {
        int item = tid + i * NTHREADS;
        int row = item >> 6, c = item & 63;
        const float4* src = (const float4*)(x + (row0 + row) * FDIM + c * 8);
        float4 f0 = src[0];
        float4 f1 = src[1];
        uint4 h;
        h.x = pack_h2(f0.x, f0.y);
        h.y = pack_h2(f0.z, f0.w);
        h.z = pack_h2(f1.x, f1.y);
        h.w = pack_h2(f1.z, f1.w);
        *(uint4*)(smem + row * 1024 + ((c ^ (row & 7)) << 4)) = h;
    }
    __syncthreads();

    // A fragment loader for global K-step (0..31)
    auto load_a = [&](uint32_t dst[2][4], int K) {
        #pragma unroll
        for (int mt = 0; mt < 2; ++mt) {
            int rowm = warp_m * 32 + mt * 16 + (lane & 15);
            int ck = K * 2 + (lane >> 4);
            ldsm_x4(dst[mt], a_base + rowm * 1024 + ((ck ^ (rowm & 7)) << 4));
        }
    };

    float acc[2][4][4];
    #pragma unroll
    for (int mt = 0; mt < 2; ++mt)
        #pragma unroll
        for (int nt = 0; nt < 4; ++nt)
            #pragma unroll
            for (int v = 0; v < 4; ++v) acc[mt][nt][v] = 0.f;

    for (int j = 0; j < 4; ++j) {
        const int Kend = 8 * (j + 1);                 // triangular K range
        // per-warp fragment pointer: element (K, N8b+nt, lane), K stride 2048 uint2
        const uint2* qp = g_Qf + ((size_t)(j * 16 + warp_n * 4) * 32) + lane;

        // prime 4-deep B register ring (K = 0..3)
        uint2 bring[4][4];
        #pragma unroll
        for (int p = 0; p < 4; ++p)
            #pragma unroll
            for (int nt = 0; nt < 4; ++nt)
                bring[p][nt] = __ldg(qp + p * 2048 + nt * 32);

        uint32_t afr[2][2][4];
        load_a(afr[0], 0);

        for (int K0 = 0; K0 < Kend; K0 += 4) {
            #pragma unroll
            for (int u = 0; u < 4; ++u) {
                const int K = K0 + u;
                const int cur = u & 1;
                if (K + 1 < Kend) load_a(afr[cur ^ 1], K + 1);
                #pragma unroll
                for (int mt = 0; mt < 2; ++mt)
                    #pragma unroll
                    for (int nt = 0; nt < 4; ++nt)
                        mma_16816(acc[mt][nt], afr[cur][mt],
                                  bring[u][nt].x, bring[u][nt].y);
                if (K + 4 < Kend) {
                    #pragma unroll
                    for (int nt = 0; nt < 4; ++nt)
                        bring[u][nt] = __ldg(qp + (K + 4) * 2048 + nt * 32);
                }
            }
        }

        // ---- fused epilogue for n-block j: out[m] += sum_n t[m,n]*x[m,n] (fp16 x from smem) ----
        #pragma unroll
        for (int mt = 0; mt < 2; ++mt) {
            #pragma unroll
            for (int h = 0; h < 2; ++h) {
                int m_loc = warp_m * 32 + mt * 16 + h * 8 + (lane >> 2);
                uint32_t rowb = a_base + m_loc * 1024;
                float s = 0.f;
                #pragma unroll
                for (int nt = 0; nt < 4; ++nt) {
                    int cch = j * 16 + warp_n * 4 + nt;   // 16B chunk holding n..n+7
                    uint32_t addr = rowb + ((cch ^ (m_loc & 7)) << 4) + (lane & 3) * 4;
                    uint32_t h2raw;
                    asm volatile("ld.shared.b32 %0, [%1];" : "=r"(h2raw) : "r"(addr));
                    float2 xv = __half22float2(*(__half2*)&h2raw);
                    s += acc[mt][nt][h * 2 + 0] * xv.x + acc[mt][nt][h * 2 + 1] * xv.y;
                }
                s += __shfl_xor_sync(0xFFFFFFFFu, s, 1);
                s += __shfl_xor_sync(0xFFFFFFFFu, s, 2);
                if ((lane & 3) == 0) atomicAdd(&partial[m_loc], s);
            }
        }
        #pragma unroll
        for (int mt = 0; mt < 2; ++mt)
            #pragma unroll
            for (int nt = 0; nt < 4; ++nt)
                #pragma unroll
                for (int v = 0; v < 4; ++v) acc[mt][nt][v] = 0.f;
    }

    __syncthreads();
    if (tid < MTILE) out[row0 + tid] = partial[tid];
}

// ---------------- launch ----------------
extern "C" void kernel_launch(void* const* d_in, const int* in_sizes, int n_in,
                              void* d_out, int out_size) {
    const float* x = (const float*)d_in[0];
    const float* Q = (const float*)d_in[1];
    if (n_in >= 2 && in_sizes[0] == FDIM * FDIM && in_sizes[1] != FDIM * FDIM) {
        const float* t = x; x = Q; Q = t;
    }
    float* out = (float*)d_out;

    cudaFuncSetAttribute(bilinear_kernel,
                         cudaFuncAttributeMaxDynamicSharedMemorySize, SMEM_TOTAL);

    convert_q_frag<<<256, 256>>>(Q);
    bilinear_kernel<<<131072 / MTILE, NTHREADS, SMEM_TOTAL>>>(x, out);
}